// round 1
// baseline (speedup 1.0000x reference)
#include <cuda_runtime.h>
#include <cuda_bf16.h>
#include <cstdint>

// Problem constants
#define NB   4
#define CC   128
#define HH   64
#define WW   64
#define LL   (HH*WW)          // 4096
#define NL   (NB*LL)          // 16384
#define GG   4
#define KK   9
#define CG   32               // CC/GG
#define OM   108              // G*3*K
#define EPSF 1e-5f

// ---------------- scratch (device globals; no allocation allowed) ----------------
__device__ float g_t   [NL*CC];     // NHWC working activation
__device__ float g_val [NL*CC];     // value projection
__device__ float g_om  [NL*OM];     // offset/mask projection
__device__ float g_samp[NL*CC];     // sampled output (pre-Wo)
__device__ float g_d   [NL*CC];     // dcn output / scratch
__device__ float g_part[2*64*CC];   // BN partial sums
__device__ float g_scale[CC];
__device__ float g_shift[CC];
__device__ float g_WcT [CC*CC];     // Wc transposed for final GEMM

// ---------------- transposes ----------------
// NCHW (n, C=128, L=4096) -> NHWC (n, L, C)
__global__ void t_c2l_kernel(const float* __restrict__ in, float* __restrict__ out) {
    __shared__ float tile[32][33];
    int n  = blockIdx.z;
    int l0 = blockIdx.x * 32;
    int c0 = blockIdx.y * 32;
    const float* ip = in  + (size_t)n * CC * LL;
    float*       op = out + (size_t)n * CC * LL;
    int tx = threadIdx.x, ty = threadIdx.y;
    #pragma unroll
    for (int j = 0; j < 32; j += 8)
        tile[ty + j][tx] = ip[(size_t)(c0 + ty + j) * LL + l0 + tx];
    __syncthreads();
    #pragma unroll
    for (int j = 0; j < 32; j += 8)
        op[(size_t)(l0 + ty + j) * CC + c0 + tx] = tile[tx][ty + j];
}

// NHWC (n, L, C) -> NCHW (n, C, L)
__global__ void t_l2c_kernel(const float* __restrict__ in, float* __restrict__ out) {
    __shared__ float tile[32][33];
    int n  = blockIdx.z;
    int l0 = blockIdx.x * 32;
    int c0 = blockIdx.y * 32;
    const float* ip = in  + (size_t)n * CC * LL;
    float*       op = out + (size_t)n * CC * LL;
    int tx = threadIdx.x, ty = threadIdx.y;
    #pragma unroll
    for (int j = 0; j < 32; j += 8)
        tile[ty + j][tx] = ip[(size_t)(l0 + ty + j) * CC + c0 + tx];
    __syncthreads();
    #pragma unroll
    for (int j = 0; j < 32; j += 8)
        op[(size_t)(c0 + ty + j) * LL + l0 + tx] = tile[tx][ty + j];
}

// Wc [o][c] -> WcT [c][o]   (128x128)
__global__ void t_wc_kernel(const float* __restrict__ in, float* __restrict__ out) {
    __shared__ float tile[32][33];
    int o0 = blockIdx.y * 32;
    int c0 = blockIdx.x * 32;
    int tx = threadIdx.x, ty = threadIdx.y;
    #pragma unroll
    for (int j = 0; j < 32; j += 8)
        tile[ty + j][tx] = in[(o0 + ty + j) * CC + c0 + tx];
    __syncthreads();
    #pragma unroll
    for (int j = 0; j < 32; j += 8)
        out[(c0 + ty + j) * CC + o0 + tx] = tile[tx][ty + j];
}

// ---------------- GEMM: C[M,N] = A[M,K] @ B[K,N] (+bias) ----------------
// BM=64 BN=64 BK=16, 256 threads, 4x4 per thread
__global__ void gemm_kernel(const float* __restrict__ A, const float* __restrict__ B,
                            const float* __restrict__ bias, float* __restrict__ C,
                            int M, int N, int K) {
    __shared__ float As[16][64];
    __shared__ float Bs[16][64];
    int tid = threadIdx.x;
    int bm0 = blockIdx.y * 64;
    int bn0 = blockIdx.x * 64;
    int tx = tid & 15, ty = tid >> 4;

    int arow = tid >> 2;
    int acol = (tid & 3) * 4;
    int brow = tid >> 4;
    int bcol = (tid & 15) * 4;

    float acc[4][4] = {};

    for (int k0 = 0; k0 < K; k0 += 16) {
        float4 av = *(const float4*)&A[(size_t)(bm0 + arow) * K + k0 + acol];
        As[acol + 0][arow] = av.x;
        As[acol + 1][arow] = av.y;
        As[acol + 2][arow] = av.z;
        As[acol + 3][arow] = av.w;
        #pragma unroll
        for (int j = 0; j < 4; j++) {
            int col = bn0 + bcol + j;
            Bs[brow][bcol + j] = (col < N) ? B[(size_t)(k0 + brow) * N + col] : 0.f;
        }
        __syncthreads();
        #pragma unroll
        for (int kk = 0; kk < 16; kk++) {
            float4 a = *(const float4*)&As[kk][ty * 4];
            float4 b = *(const float4*)&Bs[kk][tx * 4];
            float ar[4] = {a.x, a.y, a.z, a.w};
            float br[4] = {b.x, b.y, b.z, b.w};
            #pragma unroll
            for (int i = 0; i < 4; i++)
                #pragma unroll
                for (int j = 0; j < 4; j++)
                    acc[i][j] = fmaf(ar[i], br[j], acc[i][j]);
        }
        __syncthreads();
    }

    #pragma unroll
    for (int i = 0; i < 4; i++) {
        int row = bm0 + ty * 4 + i;
        #pragma unroll
        for (int j = 0; j < 4; j++) {
            int col = bn0 + tx * 4 + j;
            if (col < N) {
                float v = acc[i][j];
                if (bias) v += bias[col];
                C[(size_t)row * N + col] = v;
            }
        }
    }
}

// ---------------- deformable sampling ----------------
// one warp per (pos, g); lane = channel within group
__global__ void sample_kernel(const float* __restrict__ value, const float* __restrict__ om,
                              float* __restrict__ out) {
    int warp = (blockIdx.x * blockDim.x + threadIdx.x) >> 5;
    int lane = threadIdx.x & 31;
    if (warp >= NL * GG) return;
    int g   = warp & (GG - 1);
    int pos = warp >> 2;
    int n   = pos >> 12;   // /4096
    int l   = pos & 4095;
    int h   = l >> 6;
    int w   = l & 63;

    float omv = (lane < OM/4) ? om[(size_t)pos * OM + g * 27 + lane] : 0.f;

    const float* vbase = value + ((size_t)n * LL) * CC;
    float acc = 0.f;
    #pragma unroll
    for (int k = 0; k < KK; k++) {
        float offx = __shfl_sync(0xffffffffu, omv, 2 * k);
        float offy = __shfl_sync(0xffffffffu, omv, 2 * k + 1);
        float mk   = __shfl_sync(0xffffffffu, omv, 18 + k);
        float ly = (float)(h + k / 3 - 1) + offy;
        float lx = (float)(w + k % 3 - 1) + offx;
        float y0f = floorf(ly), x0f = floorf(lx);
        float wy = ly - y0f, wx = lx - x0f;
        int y0 = (int)y0f, x0 = (int)x0f;
        float s = 0.f;
        #pragma unroll
        for (int dy = 0; dy < 2; dy++) {
            #pragma unroll
            for (int dx = 0; dx < 2; dx++) {
                int yi = y0 + dy, xi = x0 + dx;
                float wgt = (dy ? wy : 1.f - wy) * (dx ? wx : 1.f - wx);
                bool valid = (yi >= 0) && (yi < HH) && (xi >= 0) && (xi < WW);
                int yc = min(max(yi, 0), HH - 1);
                int xc = min(max(xi, 0), WW - 1);
                float v = vbase[((size_t)(yc * WW + xc) * GG + g) * CG + lane];
                s = fmaf(v, valid ? wgt : 0.f, s);
            }
        }
        acc = fmaf(s, mk, acc);
    }
    out[((size_t)pos * GG + g) * CG + lane] = acc;
}

// ---------------- batchnorm ----------------
// stage 1: 64 blocks x 256 threads, 256 rows per block
__global__ void bn_stats_kernel(const float* __restrict__ d, float* __restrict__ part) {
    int c  = threadIdx.x & 127;
    int r0 = threadIdx.x >> 7;
    int rowbase = blockIdx.x * 256;
    float s = 0.f, s2 = 0.f;
    for (int r = r0; r < 256; r += 2) {
        float v = d[(size_t)(rowbase + r) * CC + c];
        s  += v;
        s2 = fmaf(v, v, s2);
    }
    __shared__ float sh[256], sh2[256];
    sh[threadIdx.x] = s; sh2[threadIdx.x] = s2;
    __syncthreads();
    if (threadIdx.x < 128) {
        part[blockIdx.x * CC + c]            = sh[c] + sh[c + 128];
        part[64 * CC + blockIdx.x * CC + c]  = sh2[c] + sh2[c + 128];
    }
}

// stage 2: 1 block, 128 threads -> fused scale/shift
__global__ void bn_final_kernel(const float* __restrict__ part,
                                const float* __restrict__ gamma, const float* __restrict__ beta,
                                float* __restrict__ scale, float* __restrict__ shift) {
    int c = threadIdx.x;
    float s = 0.f, s2 = 0.f;
    #pragma unroll 8
    for (int b = 0; b < 64; b++) {
        s  += part[b * CC + c];
        s2 += part[64 * CC + b * CC + c];
    }
    float mean = s * (1.f / (float)NL);
    float var  = s2 * (1.f / (float)NL) - mean * mean;
    float sc   = gamma[c] * rsqrtf(var + EPSF);
    scale[c] = sc;
    shift[c] = beta[c] - mean * sc;
}

// apply: y = d*scale+shift [, relu] [, + residual(NCHW)]
__global__ void bn_apply_kernel(const float* __restrict__ d,
                                const float* __restrict__ scale, const float* __restrict__ shift,
                                const float* __restrict__ resid_nchw,
                                float* __restrict__ out, int do_relu) {
    int idx = blockIdx.x * 256 + threadIdx.x;
    if (idx >= NL * CC) return;
    int c   = idx & 127;
    int row = idx >> 7;
    float v = fmaf(d[idx], scale[c], shift[c]);
    if (do_relu) v = fmaxf(v, 0.f);
    if (resid_nchw) {
        int n = row >> 12;
        int l = row & 4095;
        v += resid_nchw[(((size_t)n * CC + c) << 12) + l];
    }
    out[idx] = v;
}

// ---------------- host orchestration ----------------
static void run_dcn(const float* t_in, const float* Wv, const float* bv,
                    const float* Wom, const float* bom, const float* Wo,
                    float* valp, float* omp, float* sampp, float* dout) {
    dim3 gemmGridFull(2, NL / 64), gemmBlock(256);
    // value = t @ Wv + bv
    gemm_kernel<<<gemmGridFull, gemmBlock>>>(t_in, Wv, bv, valp, NL, CC, CC);
    // om = t @ Wom + bom
    gemm_kernel<<<dim3(2, NL / 64), gemmBlock>>>(t_in, Wom, bom, omp, NL, OM, CC);
    // sampling: NL*G warps, 8 warps/block
    sample_kernel<<<(NL * GG) / 8, 256>>>(valp, omp, sampp);
    // out = samp @ Wo
    gemm_kernel<<<gemmGridFull, gemmBlock>>>(sampp, Wo, nullptr, dout, NL, CC, CC);
}

extern "C" void kernel_launch(void* const* d_in, const int* in_sizes, int n_in,
                              void* d_out, int out_size) {
    const float* x     = (const float*)d_in[0];
    const float* Wv    = (const float*)d_in[1];
    const float* bv    = (const float*)d_in[2];
    const float* Wom   = (const float*)d_in[3];
    const float* bom   = (const float*)d_in[4];
    const float* Wo    = (const float*)d_in[5];
    const float* gamma = (const float*)d_in[6];
    const float* beta  = (const float*)d_in[7];
    const float* Wc    = (const float*)d_in[8];
    float* out = (float*)d_out;

    float *tp, *valp, *omp, *sampp, *dp, *partp, *scalep, *shiftp, *wctp;
    cudaGetSymbolAddress((void**)&tp,     g_t);
    cudaGetSymbolAddress((void**)&valp,   g_val);
    cudaGetSymbolAddress((void**)&omp,    g_om);
    cudaGetSymbolAddress((void**)&sampp,  g_samp);
    cudaGetSymbolAddress((void**)&dp,     g_d);
    cudaGetSymbolAddress((void**)&partp,  g_part);
    cudaGetSymbolAddress((void**)&scalep, g_scale);
    cudaGetSymbolAddress((void**)&shiftp, g_shift);
    cudaGetSymbolAddress((void**)&wctp,   g_WcT);

    dim3 tBlock(32, 8);
    dim3 tGrid(LL / 32, CC / 32, NB);

    // x NCHW -> NHWC
    t_c2l_kernel<<<tGrid, tBlock>>>(x, tp);
    // Wc -> WcT (for final y @ Wc^T)
    t_wc_kernel<<<dim3(4, 4), tBlock>>>(Wc, wctp);

    // DCN 1
    run_dcn(tp, Wv, bv, Wom, bom, Wo, valp, omp, sampp, dp);
    // BN + ReLU
    bn_stats_kernel<<<64, 256>>>(dp, partp);
    bn_final_kernel<<<1, 128>>>(partp, gamma, beta, scalep, shiftp);
    bn_apply_kernel<<<(NL * CC) / 256, 256>>>(dp, scalep, shiftp, nullptr, tp, 1);

    // DCN 2
    run_dcn(tp, Wv, bv, Wom, bom, Wo, valp, omp, sampp, dp);
    // BN + residual (x in NCHW)
    bn_stats_kernel<<<64, 256>>>(dp, partp);
    bn_final_kernel<<<1, 128>>>(partp, gamma, beta, scalep, shiftp);
    bn_apply_kernel<<<(NL * CC) / 256, 256>>>(dp, scalep, shiftp, x, tp, 0);

    // final channel mix: out_nhwc = y_nhwc @ Wc^T
    gemm_kernel<<<dim3(2, NL / 64), 256>>>(tp, wctp, nullptr, sampp, NL, CC, CC);
    // NHWC -> NCHW into d_out
    t_l2c_kernel<<<tGrid, tBlock>>>(sampp, out);
}

// round 2
// speedup vs baseline: 1.4179x; 1.4179x over previous
#include <cuda_runtime.h>
#include <cuda_bf16.h>
#include <cstdint>

// Problem constants
#define NB   4
#define CC   128
#define HH   64
#define WW   64
#define LL   (HH*WW)          // 4096
#define NL   (NB*LL)          // 16384
#define GG   4
#define KK   9
#define CG   32               // CC/GG
#define OM   108              // G*3*K
#define VOST 256              // combined value+om row stride
#define EPSF 1e-5f

// ---------------- scratch (device globals; no allocation allowed) ----------------
__device__ float g_t   [NL*CC];      // NHWC working activation
__device__ float g_vo  [NL*VOST];    // combined value(0:128) + om(128:236) projection
__device__ float g_samp[NL*CC];      // sampled output (pre-Wo)
__device__ float g_d   [NL*CC];      // dcn output
__device__ float g_part[2*128*CC];   // BN partial sums (128 gemm blocks)
__device__ float g_scale[CC];
__device__ float g_shift[CC];
__device__ float g_Wcat[CC*VOST];    // [K=128][N=256] packed Wv|Wom|0
__device__ float g_bcat[VOST];
__device__ float g_WcT [CC*CC];      // Wc transposed

// ---------------- weight packing (once per launch) ----------------
__global__ void pack_w_kernel(const float* __restrict__ Wv, const float* __restrict__ bv,
                              const float* __restrict__ Wom, const float* __restrict__ bom,
                              const float* __restrict__ Wc,
                              float* __restrict__ Wcat, float* __restrict__ bcat,
                              float* __restrict__ WcT) {
    int k = blockIdx.x;       // 0..127
    int n = threadIdx.x;      // 0..255
    float v = 0.f;
    if (n < CC)            v = Wv[k * CC + n];
    else if (n < CC + OM)  v = Wom[k * OM + (n - CC)];
    Wcat[k * VOST + n] = v;
    if (k == 0) {
        float b = 0.f;
        if (n < CC)           b = bv[n];
        else if (n < CC + OM) b = bom[n - CC];
        bcat[n] = b;
    }
    if (n < CC) WcT[k * CC + n] = Wc[n * CC + k];
}

// ---------------- transposes ----------------
__global__ void t_c2l_kernel(const float* __restrict__ in, float* __restrict__ out) {
    __shared__ float tile[32][33];
    int n = blockIdx.z, l0 = blockIdx.x * 32, c0 = blockIdx.y * 32;
    const float* ip = in  + (size_t)n * CC * LL;
    float*       op = out + (size_t)n * CC * LL;
    int tx = threadIdx.x, ty = threadIdx.y;
    #pragma unroll
    for (int j = 0; j < 32; j += 8)
        tile[ty + j][tx] = ip[(size_t)(c0 + ty + j) * LL + l0 + tx];
    __syncthreads();
    #pragma unroll
    for (int j = 0; j < 32; j += 8)
        op[(size_t)(l0 + ty + j) * CC + c0 + tx] = tile[tx][ty + j];
}

__global__ void t_l2c_kernel(const float* __restrict__ in, float* __restrict__ out) {
    __shared__ float tile[32][33];
    int n = blockIdx.z, l0 = blockIdx.x * 32, c0 = blockIdx.y * 32;
    const float* ip = in  + (size_t)n * CC * LL;
    float*       op = out + (size_t)n * CC * LL;
    int tx = threadIdx.x, ty = threadIdx.y;
    #pragma unroll
    for (int j = 0; j < 32; j += 8)
        tile[ty + j][tx] = ip[(size_t)(l0 + ty + j) * CC + c0 + tx];
    __syncthreads();
    #pragma unroll
    for (int j = 0; j < 32; j += 8)
        op[(size_t)(c0 + ty + j) * LL + l0 + tx] = tile[tx][ty + j];
}

// ---------------- GEMM: C[M,N] = A[M,128] @ B[128,N] (+bias) ----------------
// BM=128, BN=128, BK=8, 256 threads, 8x8 per thread (split 4+4), double-buffered.
// ldc = N. If part != null, also emits per-block column sums / sq-sums (N must be 128).
__global__ __launch_bounds__(256)
void gemm_kernel(const float* __restrict__ A, const float* __restrict__ B,
                 const float* __restrict__ bias, float* __restrict__ C,
                 int N, float* __restrict__ part) {
    __shared__ float As[2][8][128];
    __shared__ float Bs[2][8][128];
    int tid = threadIdx.x;
    int bm0 = blockIdx.y * 128;
    int bn0 = blockIdx.x * 128;
    int tx = tid & 15, ty = tid >> 4;

    int arow = tid >> 1, ak = (tid & 1) * 4;
    int brow = tid >> 5, bcol = (tid & 31) * 4;

    const float* Aptr = A + (size_t)(bm0 + arow) * 128 + ak;
    const float* Bptr = B + (size_t)brow * N + bn0 + bcol;

    float4 av = *(const float4*)Aptr;
    float4 bv4 = *(const float4*)Bptr;
    As[0][ak + 0][arow] = av.x; As[0][ak + 1][arow] = av.y;
    As[0][ak + 2][arow] = av.z; As[0][ak + 3][arow] = av.w;
    *(float4*)&Bs[0][brow][bcol] = bv4;
    __syncthreads();

    float acc[8][8] = {};
    #pragma unroll 2
    for (int kt = 0; kt < 16; kt++) {
        int buf = kt & 1;
        if (kt < 15) {
            av  = *(const float4*)(Aptr + (kt + 1) * 8);
            bv4 = *(const float4*)(Bptr + (size_t)(kt + 1) * 8 * N);
        }
        #pragma unroll
        for (int kk = 0; kk < 8; kk++) {
            float a[8], b[8];
            *(float4*)&a[0] = *(const float4*)&As[buf][kk][ty * 4];
            *(float4*)&a[4] = *(const float4*)&As[buf][kk][64 + ty * 4];
            *(float4*)&b[0] = *(const float4*)&Bs[buf][kk][tx * 4];
            *(float4*)&b[4] = *(const float4*)&Bs[buf][kk][64 + tx * 4];
            #pragma unroll
            for (int i = 0; i < 8; i++)
                #pragma unroll
                for (int j = 0; j < 8; j++)
                    acc[i][j] = fmaf(a[i], b[j], acc[i][j]);
        }
        if (kt < 15) {
            int nb = buf ^ 1;
            As[nb][ak + 0][arow] = av.x; As[nb][ak + 1][arow] = av.y;
            As[nb][ak + 2][arow] = av.z; As[nb][ak + 3][arow] = av.w;
            *(float4*)&Bs[nb][brow][bcol] = bv4;
            __syncthreads();
        }
    }

    float s[8] = {}, s2[8] = {};
    #pragma unroll
    for (int i = 0; i < 8; i++) {
        int ri = (i < 4) ? (ty * 4 + i) : (64 + ty * 4 + i - 4);
        float vals[8];
        #pragma unroll
        for (int j = 0; j < 8; j++) {
            int cj = (j < 4) ? (tx * 4 + j) : (64 + tx * 4 + j - 4);
            float v = acc[i][j];
            if (bias) v += bias[bn0 + cj];
            vals[j] = v;
            if (part) { s[j] += v; s2[j] = fmaf(v, v, s2[j]); }
        }
        float* crow = C + (size_t)(bm0 + ri) * N + bn0;
        *(float4*)&crow[tx * 4]      = make_float4(vals[0], vals[1], vals[2], vals[3]);
        *(float4*)&crow[64 + tx * 4] = make_float4(vals[4], vals[5], vals[6], vals[7]);
    }

    if (part) {
        __syncthreads();
        float* red  = &As[0][0][0];   // 2048 floats = 128 cols x 16 ty
        float* red2 = &Bs[0][0][0];
        #pragma unroll
        for (int j = 0; j < 8; j++) {
            int cj = (j < 4) ? (tx * 4 + j) : (64 + tx * 4 + j - 4);
            red [cj * 16 + ty] = s[j];
            red2[cj * 16 + ty] = s2[j];
        }
        __syncthreads();
        if (tid < 128) {
            float a0 = 0.f, a1 = 0.f;
            #pragma unroll
            for (int t = 0; t < 16; t++) { a0 += red[tid * 16 + t]; a1 += red2[tid * 16 + t]; }
            part[blockIdx.y * CC + tid]            = a0;
            part[128 * CC + blockIdx.y * CC + tid] = a1;
        }
    }
}

// ---------------- deformable sampling ----------------
// one warp per (pos, g); lane = channel within group. vo: [pos][256] = value|om
__global__ void sample_kernel(const float* __restrict__ vo, float* __restrict__ out) {
    int warp = (blockIdx.x * blockDim.x + threadIdx.x) >> 5;
    int lane = threadIdx.x & 31;
    if (warp >= NL * GG) return;
    int g   = warp & (GG - 1);
    int pos = warp >> 2;
    int n   = pos >> 12;
    int l   = pos & 4095;
    int h   = l >> 6;
    int w   = l & 63;

    float omv = (lane < 27) ? vo[(size_t)pos * VOST + CC + g * 27 + lane] : 0.f;

    const float* vbase = vo + (size_t)n * LL * VOST + g * CG + lane;
    float acc = 0.f;
    #pragma unroll
    for (int k = 0; k < KK; k++) {
        float offx = __shfl_sync(0xffffffffu, omv, 2 * k);
        float offy = __shfl_sync(0xffffffffu, omv, 2 * k + 1);
        float mk   = __shfl_sync(0xffffffffu, omv, 18 + k);
        float ly = (float)(h + k / 3 - 1) + offy;
        float lx = (float)(w + k % 3 - 1) + offx;
        float y0f = floorf(ly), x0f = floorf(lx);
        float wy = ly - y0f, wx = lx - x0f;
        int y0 = (int)y0f, x0 = (int)x0f;
        float s = 0.f;
        #pragma unroll
        for (int dy = 0; dy < 2; dy++) {
            #pragma unroll
            for (int dx = 0; dx < 2; dx++) {
                int yi = y0 + dy, xi = x0 + dx;
                float wgt = (dy ? wy : 1.f - wy) * (dx ? wx : 1.f - wx);
                bool valid = (yi >= 0) && (yi < HH) && (xi >= 0) && (xi < WW);
                int yc = min(max(yi, 0), HH - 1);
                int xc = min(max(xi, 0), WW - 1);
                float v = __ldg(&vbase[(size_t)(yc * WW + xc) * VOST]);
                s = fmaf(v, valid ? wgt : 0.f, s);
            }
        }
        acc = fmaf(s, mk, acc);
    }
    out[((size_t)pos * GG + g) * CG + lane] = acc;
}

// ---------------- batchnorm ----------------
__global__ void bn_final_kernel(const float* __restrict__ part,
                                const float* __restrict__ gamma, const float* __restrict__ beta,
                                float* __restrict__ scale, float* __restrict__ shift) {
    int c = threadIdx.x;
    float s = 0.f, s2 = 0.f;
    #pragma unroll 8
    for (int b = 0; b < 128; b++) {
        s  += part[b * CC + c];
        s2 += part[128 * CC + b * CC + c];
    }
    float mean = s * (1.f / (float)NL);
    float var  = s2 * (1.f / (float)NL) - mean * mean;
    float sc   = gamma[c] * rsqrtf(var + EPSF);
    scale[c] = sc;
    shift[c] = beta[c] - mean * sc;
}

// y = relu(d*scale+shift), both NHWC (coalesced)
__global__ void bn_relu_kernel(const float* __restrict__ d,
                               const float* __restrict__ scale, const float* __restrict__ shift,
                               float* __restrict__ out) {
    int idx = blockIdx.x * 256 + threadIdx.x;
    int c = idx & 127;
    out[idx] = fmaxf(fmaf(d[idx], scale[c], shift[c]), 0.f);
}

// y = d*scale+shift + x(NCHW), output NHWC; tile-transposed residual read
__global__ void bn_resid_kernel(const float* __restrict__ d,
                                const float* __restrict__ scale, const float* __restrict__ shift,
                                const float* __restrict__ x, float* __restrict__ out) {
    __shared__ float tile[32][33];
    int n = blockIdx.z, l0 = blockIdx.x * 32, c0 = blockIdx.y * 32;
    int tx = threadIdx.x, ty = threadIdx.y;
    const float* xp = x + (size_t)n * CC * LL;
    #pragma unroll
    for (int j = 0; j < 32; j += 8)
        tile[ty + j][tx] = xp[(size_t)(c0 + ty + j) * LL + l0 + tx];
    __syncthreads();
    float sc = scale[c0 + tx], sh = shift[c0 + tx];
    #pragma unroll
    for (int j = 0; j < 32; j += 8) {
        size_t idx = (size_t)(n * LL + l0 + ty + j) * CC + c0 + tx;
        out[idx] = fmaf(d[idx], sc, sh) + tile[tx][ty + j];
    }
}

// ---------------- host orchestration ----------------
extern "C" void kernel_launch(void* const* d_in, const int* in_sizes, int n_in,
                              void* d_out, int out_size) {
    const float* x     = (const float*)d_in[0];
    const float* Wv    = (const float*)d_in[1];
    const float* bv    = (const float*)d_in[2];
    const float* Wom   = (const float*)d_in[3];
    const float* bom   = (const float*)d_in[4];
    const float* Wo    = (const float*)d_in[5];
    const float* gamma = (const float*)d_in[6];
    const float* beta  = (const float*)d_in[7];
    const float* Wc    = (const float*)d_in[8];
    float* out = (float*)d_out;

    float *tp, *vop, *sampp, *dp, *partp, *scalep, *shiftp, *wcatp, *bcatp, *wctp;
    cudaGetSymbolAddress((void**)&tp,     g_t);
    cudaGetSymbolAddress((void**)&vop,    g_vo);
    cudaGetSymbolAddress((void**)&sampp,  g_samp);
    cudaGetSymbolAddress((void**)&dp,     g_d);
    cudaGetSymbolAddress((void**)&partp,  g_part);
    cudaGetSymbolAddress((void**)&scalep, g_scale);
    cudaGetSymbolAddress((void**)&shiftp, g_shift);
    cudaGetSymbolAddress((void**)&wcatp,  g_Wcat);
    cudaGetSymbolAddress((void**)&bcatp,  g_bcat);
    cudaGetSymbolAddress((void**)&wctp,   g_WcT);

    dim3 tBlock(32, 8);
    dim3 tGrid(LL / 32, CC / 32, NB);
    dim3 gemmBlock(256);
    dim3 gridVO(2, NL / 128);     // N=256
    dim3 grid128(1, NL / 128);    // N=128

    // layout prep
    t_c2l_kernel<<<tGrid, tBlock>>>(x, tp);
    pack_w_kernel<<<128, 256>>>(Wv, bv, Wom, bom, Wc, wcatp, bcatp, wctp);

    // ---- DCN block 1 ----
    gemm_kernel<<<gridVO, gemmBlock>>>(tp, wcatp, bcatp, vop, VOST, nullptr);
    sample_kernel<<<(NL * GG) / 8, 256>>>(vop, sampp);
    gemm_kernel<<<grid128, gemmBlock>>>(sampp, Wo, nullptr, dp, CC, partp);
    bn_final_kernel<<<1, 128>>>(partp, gamma, beta, scalep, shiftp);
    bn_relu_kernel<<<(NL * CC) / 256, 256>>>(dp, scalep, shiftp, tp);

    // ---- DCN block 2 ----
    gemm_kernel<<<gridVO, gemmBlock>>>(tp, wcatp, bcatp, vop, VOST, nullptr);
    sample_kernel<<<(NL * GG) / 8, 256>>>(vop, sampp);
    gemm_kernel<<<grid128, gemmBlock>>>(sampp, Wo, nullptr, dp, CC, partp);
    bn_final_kernel<<<1, 128>>>(partp, gamma, beta, scalep, shiftp);
    bn_resid_kernel<<<tGrid, tBlock>>>(dp, scalep, shiftp, x, tp);

    // ---- final channel mix + layout ----
    gemm_kernel<<<grid128, gemmBlock>>>(tp, wctp, nullptr, sampp, CC, nullptr);
    t_l2c_kernel<<<tGrid, tBlock>>>(sampp, out);
}

// round 3
// speedup vs baseline: 1.6595x; 1.1704x over previous
#include <cuda_runtime.h>
#include <cuda_bf16.h>
#include <cstdint>

// Problem constants
#define NB   4
#define CC   128
#define HH   64
#define WW   64
#define LL   (HH*WW)          // 4096
#define NL   (NB*LL)          // 16384
#define GG   4
#define KK   9
#define CG   32               // CC/GG
#define OM   108              // G*3*K
#define VOST 256              // combined value+om row stride
#define EPSF 1e-5f

// ---------------- scratch (device globals; no allocation allowed) ----------------
__device__ float g_t   [NL*CC];      // NHWC working activation
__device__ float g_vo  [NL*VOST];    // combined value(0:128) + om(128:236) projection
__device__ float g_samp[NL*CC];      // sampled output (pre-Wo)
__device__ float g_d   [NL*CC];      // dcn output
__device__ float g_part[2*128*CC];   // BN partial sums (128 gemm blocks)
__device__ float g_scale[CC];
__device__ float g_shift[CC];
__device__ float g_Wcat[CC*VOST];    // [K=128][N=256] packed Wv|Wom|0
__device__ float g_bcat[VOST];
__device__ float g_WcT [CC*CC];      // Wc transposed

// ---------------- weight packing (once per launch) ----------------
__global__ void pack_w_kernel(const float* __restrict__ Wv, const float* __restrict__ bv,
                              const float* __restrict__ Wom, const float* __restrict__ bom,
                              const float* __restrict__ Wc,
                              float* __restrict__ Wcat, float* __restrict__ bcat,
                              float* __restrict__ WcT) {
    int k = blockIdx.x;       // 0..127
    int n = threadIdx.x;      // 0..255
    float v = 0.f;
    if (n < CC)            v = Wv[k * CC + n];
    else if (n < CC + OM)  v = Wom[k * OM + (n - CC)];
    Wcat[k * VOST + n] = v;
    if (k == 0) {
        float b = 0.f;
        if (n < CC)           b = bv[n];
        else if (n < CC + OM) b = bom[n - CC];
        bcat[n] = b;
    }
    if (n < CC) WcT[k * CC + n] = Wc[n * CC + k];
}

// ---------------- transposes ----------------
__global__ void t_c2l_kernel(const float* __restrict__ in, float* __restrict__ out) {
    __shared__ float tile[32][33];
    int n = blockIdx.z, l0 = blockIdx.x * 32, c0 = blockIdx.y * 32;
    const float* ip = in  + (size_t)n * CC * LL;
    float*       op = out + (size_t)n * CC * LL;
    int tx = threadIdx.x, ty = threadIdx.y;
    #pragma unroll
    for (int j = 0; j < 32; j += 8)
        tile[ty + j][tx] = ip[(size_t)(c0 + ty + j) * LL + l0 + tx];
    __syncthreads();
    #pragma unroll
    for (int j = 0; j < 32; j += 8)
        op[(size_t)(l0 + ty + j) * CC + c0 + tx] = tile[tx][ty + j];
}

__global__ void t_l2c_kernel(const float* __restrict__ in, float* __restrict__ out) {
    __shared__ float tile[32][33];
    int n = blockIdx.z, l0 = blockIdx.x * 32, c0 = blockIdx.y * 32;
    const float* ip = in  + (size_t)n * CC * LL;
    float*       op = out + (size_t)n * CC * LL;
    int tx = threadIdx.x, ty = threadIdx.y;
    #pragma unroll
    for (int j = 0; j < 32; j += 8)
        tile[ty + j][tx] = ip[(size_t)(l0 + ty + j) * CC + c0 + tx];
    __syncthreads();
    #pragma unroll
    for (int j = 0; j < 32; j += 8)
        op[(size_t)(c0 + ty + j) * LL + l0 + tx] = tile[tx][ty + j];
}

// ---------------- GEMM: C[M,N] = A[M,128] @ B[128,N] (+bias) ----------------
// BM=128, BN=128, BK=8, 256 threads, 8x8 per thread, double-buffered.
// Optional A transform: a' = relu(a*ascale[k]+ashift[k]) applied at smem staging.
// Optional part output: per-block column sums/sq-sums for BN (requires N==128).
__device__ __forceinline__ float4 a_xform(float4 v, const float* sc, const float* sh, int kidx) {
    float4 s = *(const float4*)&sc[kidx];
    float4 t = *(const float4*)&sh[kidx];
    v.x = fmaxf(fmaf(v.x, s.x, t.x), 0.f);
    v.y = fmaxf(fmaf(v.y, s.y, t.y), 0.f);
    v.z = fmaxf(fmaf(v.z, s.z, t.z), 0.f);
    v.w = fmaxf(fmaf(v.w, s.w, t.w), 0.f);
    return v;
}

__global__ __launch_bounds__(256)
void gemm_kernel(const float* __restrict__ A, const float* __restrict__ B,
                 const float* __restrict__ bias, float* __restrict__ C,
                 int N, float* __restrict__ part,
                 const float* __restrict__ ascale, const float* __restrict__ ashift) {
    __shared__ float As[2][8][128];
    __shared__ float Bs[2][8][128];
    int tid = threadIdx.x;
    int bm0 = blockIdx.y * 128;
    int bn0 = blockIdx.x * 128;
    int tx = tid & 15, ty = tid >> 4;

    int arow = tid >> 1, ak = (tid & 1) * 4;
    int brow = tid >> 5, bcol = (tid & 31) * 4;

    const float* Aptr = A + (size_t)(bm0 + arow) * 128 + ak;
    const float* Bptr = B + (size_t)brow * N + bn0 + bcol;

    float4 av = *(const float4*)Aptr;
    float4 bv4 = *(const float4*)Bptr;
    if (ascale) av = a_xform(av, ascale, ashift, ak);
    As[0][ak + 0][arow] = av.x; As[0][ak + 1][arow] = av.y;
    As[0][ak + 2][arow] = av.z; As[0][ak + 3][arow] = av.w;
    *(float4*)&Bs[0][brow][bcol] = bv4;
    __syncthreads();

    float acc[8][8] = {};
    #pragma unroll 2
    for (int kt = 0; kt < 16; kt++) {
        int buf = kt & 1;
        if (kt < 15) {
            av  = *(const float4*)(Aptr + (kt + 1) * 8);
            bv4 = *(const float4*)(Bptr + (size_t)(kt + 1) * 8 * N);
            if (ascale) av = a_xform(av, ascale, ashift, (kt + 1) * 8 + ak);
        }
        #pragma unroll
        for (int kk = 0; kk < 8; kk++) {
            float a[8], b[8];
            *(float4*)&a[0] = *(const float4*)&As[buf][kk][ty * 4];
            *(float4*)&a[4] = *(const float4*)&As[buf][kk][64 + ty * 4];
            *(float4*)&b[0] = *(const float4*)&Bs[buf][kk][tx * 4];
            *(float4*)&b[4] = *(const float4*)&Bs[buf][kk][64 + tx * 4];
            #pragma unroll
            for (int i = 0; i < 8; i++)
                #pragma unroll
                for (int j = 0; j < 8; j++)
                    acc[i][j] = fmaf(a[i], b[j], acc[i][j]);
        }
        if (kt < 15) {
            int nb = buf ^ 1;
            As[nb][ak + 0][arow] = av.x; As[nb][ak + 1][arow] = av.y;
            As[nb][ak + 2][arow] = av.z; As[nb][ak + 3][arow] = av.w;
            *(float4*)&Bs[nb][brow][bcol] = bv4;
            __syncthreads();
        }
    }

    float s[8] = {}, s2[8] = {};
    #pragma unroll
    for (int i = 0; i < 8; i++) {
        int ri = (i < 4) ? (ty * 4 + i) : (64 + ty * 4 + i - 4);
        float vals[8];
        #pragma unroll
        for (int j = 0; j < 8; j++) {
            int cj = (j < 4) ? (tx * 4 + j) : (64 + tx * 4 + j - 4);
            float v = acc[i][j];
            if (bias) v += bias[bn0 + cj];
            vals[j] = v;
            if (part) { s[j] += v; s2[j] = fmaf(v, v, s2[j]); }
        }
        float* crow = C + (size_t)(bm0 + ri) * N + bn0;
        *(float4*)&crow[tx * 4]      = make_float4(vals[0], vals[1], vals[2], vals[3]);
        *(float4*)&crow[64 + tx * 4] = make_float4(vals[4], vals[5], vals[6], vals[7]);
    }

    if (part) {
        __syncthreads();
        float* red  = &As[0][0][0];
        float* red2 = &Bs[0][0][0];
        #pragma unroll
        for (int j = 0; j < 8; j++) {
            int cj = (j < 4) ? (tx * 4 + j) : (64 + tx * 4 + j - 4);
            red [cj * 16 + ty] = s[j];
            red2[cj * 16 + ty] = s2[j];
        }
        __syncthreads();
        if (tid < 128) {
            float a0 = 0.f, a1 = 0.f;
            #pragma unroll
            for (int t = 0; t < 16; t++) { a0 += red[tid * 16 + t]; a1 += red2[tid * 16 + t]; }
            part[blockIdx.y * CC + tid]            = a0;
            part[128 * CC + blockIdx.y * CC + tid] = a1;
        }
    }
}

// ---------------- deformable sampling (vectorized) ----------------
// one warp per position, all 4 groups. lane = g*8+q; each lane handles 4 channels.
__global__ __launch_bounds__(256)
void sample_kernel(const float* __restrict__ vo, float* __restrict__ out) {
    __shared__ float s_om[8][OM];
    int wid  = threadIdx.x >> 5;
    int lane = threadIdx.x & 31;
    int pos  = blockIdx.x * 8 + wid;
    int g = lane >> 3;
    int n = pos >> 12;
    int l = pos & 4095;
    int h = l >> 6;
    int w = l & 63;

    // stage this position's 108 offset/mask scalars
    const float* omp = vo + (size_t)pos * VOST + CC;
    for (int i = lane; i < OM; i += 32) s_om[wid][i] = omp[i];
    __syncwarp();

    const float* vbase = vo + (size_t)n * (LL * VOST) + (lane << 2);  // g*32+q*4 == lane*4
    const float* omg = &s_om[wid][g * 27];

    float ax = 0.f, ay = 0.f, az = 0.f, aw = 0.f;
    #pragma unroll
    for (int k = 0; k < KK; k++) {
        float offx = omg[2 * k];
        float offy = omg[2 * k + 1];
        float mk   = omg[18 + k];
        float ly = (float)(h + k / 3 - 1) + offy;
        float lx = (float)(w + k % 3 - 1) + offx;
        float y0f = floorf(ly), x0f = floorf(lx);
        float wy = ly - y0f, wx = lx - x0f;
        int y0 = (int)y0f, x0 = (int)x0f;

        float sx, sy, sz, sw;
        if (y0 >= 0 && y0 < HH - 1 && x0 >= 0 && x0 < WW - 1) {
            // interior fast path: no clamps, no masks
            const float* p = vbase + (y0 << 14) + (x0 << 8);
            float4 v00 = *(const float4*)p;
            float4 v01 = *(const float4*)(p + VOST);
            float4 v10 = *(const float4*)(p + (WW * VOST));
            float4 v11 = *(const float4*)(p + (WW * VOST + VOST));
            float w00 = (1.f - wy) * (1.f - wx);
            float w01 = (1.f - wy) * wx;
            float w10 = wy * (1.f - wx);
            float w11 = wy * wx;
            sx = v00.x * w00 + v01.x * w01 + v10.x * w10 + v11.x * w11;
            sy = v00.y * w00 + v01.y * w01 + v10.y * w10 + v11.y * w11;
            sz = v00.z * w00 + v01.z * w01 + v10.z * w10 + v11.z * w11;
            sw = v00.w * w00 + v01.w * w01 + v10.w * w10 + v11.w * w11;
        } else {
            sx = sy = sz = sw = 0.f;
            #pragma unroll
            for (int dy = 0; dy < 2; dy++) {
                #pragma unroll
                for (int dx = 0; dx < 2; dx++) {
                    int yi = y0 + dy, xi = x0 + dx;
                    float wgt = (dy ? wy : 1.f - wy) * (dx ? wx : 1.f - wx);
                    bool valid = (yi >= 0) && (yi < HH) && (xi >= 0) && (xi < WW);
                    if (!valid) wgt = 0.f;
                    int yc = min(max(yi, 0), HH - 1);
                    int xc = min(max(xi, 0), WW - 1);
                    float4 v = *(const float4*)(vbase + (yc << 14) + (xc << 8));
                    sx = fmaf(v.x, wgt, sx);
                    sy = fmaf(v.y, wgt, sy);
                    sz = fmaf(v.z, wgt, sz);
                    sw = fmaf(v.w, wgt, sw);
                }
            }
        }
        ax = fmaf(sx, mk, ax);
        ay = fmaf(sy, mk, ay);
        az = fmaf(sz, mk, az);
        aw = fmaf(sw, mk, aw);
    }
    *(float4*)&out[(size_t)pos * CC + (lane << 2)] = make_float4(ax, ay, az, aw);
}

// ---------------- batchnorm ----------------
__global__ void bn_final_kernel(const float* __restrict__ part,
                                const float* __restrict__ gamma, const float* __restrict__ beta,
                                float* __restrict__ scale, float* __restrict__ shift) {
    int c = threadIdx.x;
    float s = 0.f, s2 = 0.f;
    #pragma unroll 8
    for (int b = 0; b < 128; b++) {
        s  += part[b * CC + c];
        s2 += part[128 * CC + b * CC + c];
    }
    float mean = s * (1.f / (float)NL);
    float var  = s2 * (1.f / (float)NL) - mean * mean;
    float sc   = gamma[c] * rsqrtf(var + EPSF);
    scale[c] = sc;
    shift[c] = beta[c] - mean * sc;
}

// y = d*scale+shift + x(NCHW), output NHWC; tile-transposed residual read
__global__ void bn_resid_kernel(const float* __restrict__ d,
                                const float* __restrict__ scale, const float* __restrict__ shift,
                                const float* __restrict__ x, float* __restrict__ out) {
    __shared__ float tile[32][33];
    int n = blockIdx.z, l0 = blockIdx.x * 32, c0 = blockIdx.y * 32;
    int tx = threadIdx.x, ty = threadIdx.y;
    const float* xp = x + (size_t)n * CC * LL;
    #pragma unroll
    for (int j = 0; j < 32; j += 8)
        tile[ty + j][tx] = xp[(size_t)(c0 + ty + j) * LL + l0 + tx];
    __syncthreads();
    float sc = scale[c0 + tx], sh = shift[c0 + tx];
    #pragma unroll
    for (int j = 0; j < 32; j += 8) {
        size_t idx = (size_t)(n * LL + l0 + ty + j) * CC + c0 + tx;
        out[idx] = fmaf(d[idx], sc, sh) + tile[tx][ty + j];
    }
}

// ---------------- host orchestration ----------------
extern "C" void kernel_launch(void* const* d_in, const int* in_sizes, int n_in,
                              void* d_out, int out_size) {
    const float* x     = (const float*)d_in[0];
    const float* Wv    = (const float*)d_in[1];
    const float* bv    = (const float*)d_in[2];
    const float* Wom   = (const float*)d_in[3];
    const float* bom   = (const float*)d_in[4];
    const float* Wo    = (const float*)d_in[5];
    const float* gamma = (const float*)d_in[6];
    const float* beta  = (const float*)d_in[7];
    const float* Wc    = (const float*)d_in[8];
    float* out = (float*)d_out;

    float *tp, *vop, *sampp, *dp, *partp, *scalep, *shiftp, *wcatp, *bcatp, *wctp;
    cudaGetSymbolAddress((void**)&tp,     g_t);
    cudaGetSymbolAddress((void**)&vop,    g_vo);
    cudaGetSymbolAddress((void**)&sampp,  g_samp);
    cudaGetSymbolAddress((void**)&dp,     g_d);
    cudaGetSymbolAddress((void**)&partp,  g_part);
    cudaGetSymbolAddress((void**)&scalep, g_scale);
    cudaGetSymbolAddress((void**)&shiftp, g_shift);
    cudaGetSymbolAddress((void**)&wcatp,  g_Wcat);
    cudaGetSymbolAddress((void**)&bcatp,  g_bcat);
    cudaGetSymbolAddress((void**)&wctp,   g_WcT);

    dim3 tBlock(32, 8);
    dim3 tGrid(LL / 32, CC / 32, NB);
    dim3 gemmBlock(256);
    dim3 gridVO(2, NL / 128);     // N=256
    dim3 grid128(1, NL / 128);    // N=128

    // layout prep
    t_c2l_kernel<<<tGrid, tBlock>>>(x, tp);
    pack_w_kernel<<<128, 256>>>(Wv, bv, Wom, bom, Wc, wcatp, bcatp, wctp);

    // ---- DCN block 1 ----
    gemm_kernel<<<gridVO, gemmBlock>>>(tp, wcatp, bcatp, vop, VOST, nullptr, nullptr, nullptr);
    sample_kernel<<<NL / 8, 256>>>(vop, sampp);
    gemm_kernel<<<grid128, gemmBlock>>>(sampp, Wo, nullptr, dp, CC, partp, nullptr, nullptr);
    bn_final_kernel<<<1, 128>>>(partp, gamma, beta, scalep, shiftp);

    // ---- DCN block 2 (BN+ReLU fused into A-load of the vo GEMM) ----
    gemm_kernel<<<gridVO, gemmBlock>>>(dp, wcatp, bcatp, vop, VOST, nullptr, scalep, shiftp);
    sample_kernel<<<NL / 8, 256>>>(vop, sampp);
    gemm_kernel<<<grid128, gemmBlock>>>(sampp, Wo, nullptr, dp, CC, partp, nullptr, nullptr);
    bn_final_kernel<<<1, 128>>>(partp, gamma, beta, scalep, shiftp);
    bn_resid_kernel<<<tGrid, tBlock>>>(dp, scalep, shiftp, x, tp);

    // ---- final channel mix + layout ----
    gemm_kernel<<<grid128, gemmBlock>>>(tp, wctp, nullptr, sampp, CC, nullptr, nullptr, nullptr);
    t_l2c_kernel<<<tGrid, tBlock>>>(sampp, out);
}

// round 5
// speedup vs baseline: 1.9680x; 1.1859x over previous
#include <cuda_runtime.h>
#include <cuda_bf16.h>
#include <cstdint>

// Problem constants
#define NB   4
#define CC   128
#define HH   64
#define WW   64
#define LL   (HH*WW)          // 4096
#define NL   (NB*LL)          // 16384
#define GG   4
#define KK   9
#define CG   32               // CC/GG
#define OM   108              // G*3*K
#define VOST 256              // combined value+om row stride
#define EPSF 1e-5f
#define LDA  136              // padded bf16 row length (272B = 68 words -> conflict-free ldmatrix)

__device__ __forceinline__ uint32_t smem_to_u32(const void* p) {
    uint32_t a;
    asm("{ .reg .u64 t; cvta.to.shared.u64 t, %1; cvt.u32.u64 %0, t; }" : "=r"(a) : "l"(p));
    return a;
}

__device__ __forceinline__ void ldm_x4(uint32_t addr, uint32_t& r0, uint32_t& r1,
                                       uint32_t& r2, uint32_t& r3) {
    asm volatile("ldmatrix.sync.aligned.m8n8.x4.shared.b16 {%0,%1,%2,%3}, [%4];"
                 : "=r"(r0), "=r"(r1), "=r"(r2), "=r"(r3) : "r"(addr));
}

__device__ __forceinline__ void mma16816(float* d, const uint32_t* a, const uint32_t* b) {
    asm volatile(
        "mma.sync.aligned.m16n8k16.row.col.f32.bf16.bf16.f32 "
        "{%0,%1,%2,%3}, {%4,%5,%6,%7}, {%8,%9}, {%0,%1,%2,%3};"
        : "+f"(d[0]), "+f"(d[1]), "+f"(d[2]), "+f"(d[3])
        : "r"(a[0]), "r"(a[1]), "r"(a[2]), "r"(a[3]), "r"(b[0]), "r"(b[1]));
}

// ---------------- scratch (device globals; no allocation allowed) ----------------
__device__ float g_t   [NL*CC];
__device__ float g_vo  [NL*VOST];
__device__ float g_samp[NL*CC];
__device__ float g_d   [NL*CC];
__device__ float g_part[2*64*CC];
__device__ float g_scale[CC];
__device__ float g_shift[CC];
__device__ float g_bcat[VOST];
__device__ __nv_bfloat16 g_WcatT_hi[VOST*CC];  // [n=256][k=128] = {Wv|Wom}^T
__device__ __nv_bfloat16 g_WcatT_lo[VOST*CC];
__device__ __nv_bfloat16 g_WoT_hi[CC*CC];      // [n][k] = Wo[k][n]
__device__ __nv_bfloat16 g_WoT_lo[CC*CC];
__device__ __nv_bfloat16 g_Wc_hi[CC*CC];       // [o][c] = Wc as-is
__device__ __nv_bfloat16 g_Wc_lo[CC*CC];

// ---------------- weight packing + bf16 split (once per launch) ----------------
__device__ __forceinline__ void split_store(float v, __nv_bfloat16* hi, __nv_bfloat16* lo, int idx) {
    __nv_bfloat16 h = __float2bfloat16_rn(v);
    hi[idx] = h;
    lo[idx] = __float2bfloat16_rn(v - __bfloat162float(h));
}

__global__ void pack_w_kernel(const float* __restrict__ Wv, const float* __restrict__ bv,
                              const float* __restrict__ Wom, const float* __restrict__ bom,
                              const float* __restrict__ Wo, const float* __restrict__ Wc,
                              float* __restrict__ bcat) {
    int n = blockIdx.x;    // 0..255
    int k = threadIdx.x;   // 0..127
    float v = 0.f;
    if (n < CC)           v = Wv[k * CC + n];
    else if (n < CC + OM) v = Wom[k * OM + (n - CC)];
    split_store(v, g_WcatT_hi, g_WcatT_lo, n * CC + k);
    if (n < CC) {
        split_store(Wo[k * CC + n], g_WoT_hi, g_WoT_lo, n * CC + k);
        split_store(Wc[n * CC + k], g_Wc_hi,  g_Wc_lo,  n * CC + k);
    }
    if (k == 0) {
        float b = 0.f;
        if (n < CC)           b = bv[n];
        else if (n < CC + OM) b = bom[n - CC];
        bcat[n] = b;
    }
}

// ---------------- transposes ----------------
__global__ void t_c2l_kernel(const float* __restrict__ in, float* __restrict__ out) {
    __shared__ float tile[32][33];
    int n = blockIdx.z, l0 = blockIdx.x * 32, c0 = blockIdx.y * 32;
    const float* ip = in  + (size_t)n * CC * LL;
    float*       op = out + (size_t)n * CC * LL;
    int tx = threadIdx.x, ty = threadIdx.y;
    #pragma unroll
    for (int j = 0; j < 32; j += 8)
        tile[ty + j][tx] = ip[(size_t)(c0 + ty + j) * LL + l0 + tx];
    __syncthreads();
    #pragma unroll
    for (int j = 0; j < 32; j += 8)
        op[(size_t)(l0 + ty + j) * CC + c0 + tx] = tile[tx][ty + j];
}

__global__ void t_l2c_kernel(const float* __restrict__ in, float* __restrict__ out) {
    __shared__ float tile[32][33];
    int n = blockIdx.z, l0 = blockIdx.x * 32, c0 = blockIdx.y * 32;
    const float* ip = in  + (size_t)n * CC * LL;
    float*       op = out + (size_t)n * CC * LL;
    int tx = threadIdx.x, ty = threadIdx.y;
    #pragma unroll
    for (int j = 0; j < 32; j += 8)
        tile[ty + j][tx] = ip[(size_t)(l0 + ty + j) * CC + c0 + tx];
    __syncthreads();
    #pragma unroll
    for (int j = 0; j < 32; j += 8)
        op[(size_t)(c0 + ty + j) * LL + l0 + tx] = tile[tx][ty + j];
}

// ---------------- HMMA GEMM: C[M,N] = A[M,128] @ B^T (+bias) ----------------
// bf16 split: D = Ahi*Bhi + Alo*Bhi + Ahi*Blo, fp32 accumulate.
// CTA = 128x128 tile, 256 threads (8 warps, 2M x 4N), warp = 64x32.
// Optional A transform relu(a*ascale[k]+ashift[k]) fused at staging.
__global__ __launch_bounds__(256, 1)
void mma_gemm_kernel(const float* __restrict__ A,
                     const __nv_bfloat16* __restrict__ Bhi,
                     const __nv_bfloat16* __restrict__ Blo,
                     const float* __restrict__ bias,
                     float* __restrict__ C, int ldc,
                     const float* __restrict__ ascale, const float* __restrict__ ashift) {
    extern __shared__ __nv_bfloat16 sm[];
    __nv_bfloat16* sAh = sm;                 // [128][LDA]
    __nv_bfloat16* sAl = sAh + 128 * LDA;
    __nv_bfloat16* sBh = sAl + 128 * LDA;
    __nv_bfloat16* sBl = sBh + 128 * LDA;

    int tid = threadIdx.x;
    int bm0 = blockIdx.y * 128;
    int bn0 = blockIdx.x * 128;

    // ---- stage A: fp32 -> bf16 hi/lo (+ optional BN+ReLU) ----
    {
        int row = tid >> 1, kh = (tid & 1) * 64;
        const float* ar = A + (size_t)(bm0 + row) * 128 + kh;
        __nv_bfloat16* dh = sAh + row * LDA + kh;
        __nv_bfloat16* dl = sAl + row * LDA + kh;
        #pragma unroll
        for (int i = 0; i < 64; i += 8) {
            float v[8];
            *(float4*)&v[0] = *(const float4*)(ar + i);
            *(float4*)&v[4] = *(const float4*)(ar + i + 4);
            if (ascale) {
                #pragma unroll
                for (int j = 0; j < 8; j++)
                    v[j] = fmaxf(fmaf(v[j], ascale[kh + i + j], ashift[kh + i + j]), 0.f);
            }
            uint32_t h[4], l[4];
            #pragma unroll
            for (int p = 0; p < 4; p++) {
                __nv_bfloat16 h0 = __float2bfloat16_rn(v[2 * p]);
                __nv_bfloat16 h1 = __float2bfloat16_rn(v[2 * p + 1]);
                float l0 = v[2 * p] - __bfloat162float(h0);
                float l1 = v[2 * p + 1] - __bfloat162float(h1);
                __nv_bfloat162 hp; hp.x = h0; hp.y = h1;
                __nv_bfloat162 lp; lp.x = __float2bfloat16_rn(l0); lp.y = __float2bfloat16_rn(l1);
                h[p] = *reinterpret_cast<uint32_t*>(&hp);
                l[p] = *reinterpret_cast<uint32_t*>(&lp);
            }
            *(uint4*)(dh + i) = make_uint4(h[0], h[1], h[2], h[3]);
            *(uint4*)(dl + i) = make_uint4(l[0], l[1], l[2], l[3]);
        }
    }
    // ---- stage B: bf16 copy ----
    {
        int row = tid >> 1, kh = (tid & 1) * 64;
        const uint4* bh = (const uint4*)(Bhi + (size_t)(bn0 + row) * 128 + kh);
        const uint4* bl = (const uint4*)(Blo + (size_t)(bn0 + row) * 128 + kh);
        uint4* dh = (uint4*)(sBh + row * LDA + kh);
        uint4* dl = (uint4*)(sBl + row * LDA + kh);
        #pragma unroll
        for (int i = 0; i < 8; i++) { dh[i] = bh[i]; dl[i] = bl[i]; }
    }
    __syncthreads();

    int wid = tid >> 5, lane = tid & 31;
    int wm = (wid >> 2) * 64;      // warp M origin within tile
    int wn = (wid & 3) * 32;       // warp N origin within tile

    uint32_t baseA = smem_to_u32(sAh);
    uint32_t dAlo  = (uint32_t)(128 * LDA * 2);   // byte delta sAh->sAl
    uint32_t baseB = smem_to_u32(sBh);
    uint32_t dBlo  = dAlo;

    // per-lane ldmatrix addresses (byte offsets within a [*][LDA] bf16 array)
    // A x4: matrices (m0,k0),(m0+8,k0),(m0,k0+8),(m0+8,k0+8)
    int a_r = (lane & 7) + ((lane >> 3) & 1) * 8;
    int a_c = ((lane >> 4) & 1) * 8;
    // B x4 over two n-tiles: (n0,k0),(n0,k0+8),(n0+8,k0),(n0+8,k0+8)
    int b_r = (lane & 7) + ((lane >> 4) & 1) * 8;
    int b_c = ((lane >> 3) & 1) * 8;

    float acc[4][4][4];
    #pragma unroll
    for (int i = 0; i < 4; i++)
        #pragma unroll
        for (int j = 0; j < 4; j++)
            #pragma unroll
            for (int q = 0; q < 4; q++) acc[i][j][q] = 0.f;

    #pragma unroll
    for (int k0 = 0; k0 < 128; k0 += 16) {
        uint32_t ah[4][4], al[4][4], bh[4][2], bl[4][2];
        #pragma unroll
        for (int mi = 0; mi < 4; mi++) {
            uint32_t off = (uint32_t)((wm + mi * 16 + a_r) * LDA + k0 + a_c) * 2;
            ldm_x4(baseA + off,        ah[mi][0], ah[mi][1], ah[mi][2], ah[mi][3]);
            ldm_x4(baseA + dAlo + off, al[mi][0], al[mi][1], al[mi][2], al[mi][3]);
        }
        #pragma unroll
        for (int p = 0; p < 2; p++) {
            uint32_t off = (uint32_t)((wn + p * 16 + b_r) * LDA + k0 + b_c) * 2;
            ldm_x4(baseB + off,        bh[2*p][0], bh[2*p][1], bh[2*p+1][0], bh[2*p+1][1]);
            ldm_x4(baseB + dBlo + off, bl[2*p][0], bl[2*p][1], bl[2*p+1][0], bl[2*p+1][1]);
        }
        #pragma unroll
        for (int mi = 0; mi < 4; mi++)
            #pragma unroll
            for (int nj = 0; nj < 4; nj++) {
                mma16816(acc[mi][nj], ah[mi], bh[nj]);
                mma16816(acc[mi][nj], al[mi], bh[nj]);
                mma16816(acc[mi][nj], ah[mi], bl[nj]);
            }
    }

    // ---- epilogue ----
    int q = lane >> 2, idx = lane & 3;
    #pragma unroll
    for (int mi = 0; mi < 4; mi++) {
        int r0 = bm0 + wm + mi * 16 + q;
        #pragma unroll
        for (int nj = 0; nj < 4; nj++) {
            int c = bn0 + wn + nj * 8 + idx * 2;
            float2 v0 = make_float2(acc[mi][nj][0], acc[mi][nj][1]);
            float2 v1 = make_float2(acc[mi][nj][2], acc[mi][nj][3]);
            if (bias) {
                float2 b = *(const float2*)&bias[c];
                v0.x += b.x; v0.y += b.y; v1.x += b.x; v1.y += b.y;
            }
            *(float2*)&C[(size_t)r0 * ldc + c]       = v0;
            *(float2*)&C[(size_t)(r0 + 8) * ldc + c] = v1;
        }
    }
}

// ---------------- deformable sampling (vectorized) ----------------
__global__ __launch_bounds__(256)
void sample_kernel(const float* __restrict__ vo, float* __restrict__ out) {
    __shared__ float s_om[8][OM];
    int wid  = threadIdx.x >> 5;
    int lane = threadIdx.x & 31;
    int pos  = blockIdx.x * 8 + wid;
    int g = lane >> 3;
    int n = pos >> 12;
    int l = pos & 4095;
    int h = l >> 6;
    int w = l & 63;

    const float* omp = vo + (size_t)pos * VOST + CC;
    for (int i = lane; i < OM; i += 32) s_om[wid][i] = omp[i];
    __syncwarp();

    const float* vbase = vo + (size_t)n * (LL * VOST) + (lane << 2);
    const float* omg = &s_om[wid][g * 27];

    float ax = 0.f, ay = 0.f, az = 0.f, aw = 0.f;
    #pragma unroll
    for (int k = 0; k < KK; k++) {
        float offx = omg[2 * k];
        float offy = omg[2 * k + 1];
        float mk   = omg[18 + k];
        float ly = (float)(h + k / 3 - 1) + offy;
        float lx = (float)(w + k % 3 - 1) + offx;
        float y0f = floorf(ly), x0f = floorf(lx);
        float wy = ly - y0f, wx = lx - x0f;
        int y0 = (int)y0f, x0 = (int)x0f;

        float sx, sy, sz, sw;
        if (y0 >= 0 && y0 < HH - 1 && x0 >= 0 && x0 < WW - 1) {
            const float* p = vbase + (y0 << 14) + (x0 << 8);
            float4 v00 = *(const float4*)p;
            float4 v01 = *(const float4*)(p + VOST);
            float4 v10 = *(const float4*)(p + (WW * VOST));
            float4 v11 = *(const float4*)(p + (WW * VOST + VOST));
            float w00 = (1.f - wy) * (1.f - wx);
            float w01 = (1.f - wy) * wx;
            float w10 = wy * (1.f - wx);
            float w11 = wy * wx;
            sx = v00.x * w00 + v01.x * w01 + v10.x * w10 + v11.x * w11;
            sy = v00.y * w00 + v01.y * w01 + v10.y * w10 + v11.y * w11;
            sz = v00.z * w00 + v01.z * w01 + v10.z * w10 + v11.z * w11;
            sw = v00.w * w00 + v01.w * w01 + v10.w * w10 + v11.w * w11;
        } else {
            sx = sy = sz = sw = 0.f;
            #pragma unroll
            for (int dy = 0; dy < 2; dy++) {
                #pragma unroll
                for (int dx = 0; dx < 2; dx++) {
                    int yi = y0 + dy, xi = x0 + dx;
                    float wgt = (dy ? wy : 1.f - wy) * (dx ? wx : 1.f - wx);
                    bool valid = (yi >= 0) && (yi < HH) && (xi >= 0) && (xi < WW);
                    if (!valid) wgt = 0.f;
                    int yc = min(max(yi, 0), HH - 1);
                    int xc = min(max(xi, 0), WW - 1);
                    float4 v = *(const float4*)(vbase + (yc << 14) + (xc << 8));
                    sx = fmaf(v.x, wgt, sx);
                    sy = fmaf(v.y, wgt, sy);
                    sz = fmaf(v.z, wgt, sz);
                    sw = fmaf(v.w, wgt, sw);
                }
            }
        }
        ax = fmaf(sx, mk, ax);
        ay = fmaf(sy, mk, ay);
        az = fmaf(sz, mk, az);
        aw = fmaf(sw, mk, aw);
    }
    *(float4*)&out[(size_t)pos * CC + (lane << 2)] = make_float4(ax, ay, az, aw);
}

// ---------------- batchnorm ----------------
__global__ void bn_stats_kernel(const float* __restrict__ d, float* __restrict__ part) {
    int c  = threadIdx.x & 127;
    int r0 = threadIdx.x >> 7;
    int rowbase = blockIdx.x * 256;
    float s = 0.f, s2 = 0.f;
    for (int r = r0; r < 256; r += 2) {
        float v = d[(size_t)(rowbase + r) * CC + c];
        s  += v;
        s2 = fmaf(v, v, s2);
    }
    __shared__ float sh[256], sh2[256];
    sh[threadIdx.x] = s; sh2[threadIdx.x] = s2;
    __syncthreads();
    if (threadIdx.x < 128) {
        part[blockIdx.x * CC + c]           = sh[c] + sh[c + 128];
        part[64 * CC + blockIdx.x * CC + c] = sh2[c] + sh2[c + 128];
    }
}

__global__ void bn_final_kernel(const float* __restrict__ part,
                                const float* __restrict__ gamma, const float* __restrict__ beta,
                                float* __restrict__ scale, float* __restrict__ shift) {
    int c = threadIdx.x;
    float s = 0.f, s2 = 0.f;
    #pragma unroll 8
    for (int b = 0; b < 64; b++) {
        s  += part[b * CC + c];
        s2 += part[64 * CC + b * CC + c];
    }
    float mean = s * (1.f / (float)NL);
    float var  = s2 * (1.f / (float)NL) - mean * mean;
    float sc   = gamma[c] * rsqrtf(var + EPSF);
    scale[c] = sc;
    shift[c] = beta[c] - mean * sc;
}

__global__ void bn_resid_kernel(const float* __restrict__ d,
                                const float* __restrict__ scale, const float* __restrict__ shift,
                                const float* __restrict__ x, float* __restrict__ out) {
    __shared__ float tile[32][33];
    int n = blockIdx.z, l0 = blockIdx.x * 32, c0 = blockIdx.y * 32;
    int tx = threadIdx.x, ty = threadIdx.y;
    const float* xp = x + (size_t)n * CC * LL;
    #pragma unroll
    for (int j = 0; j < 32; j += 8)
        tile[ty + j][tx] = xp[(size_t)(c0 + ty + j) * LL + l0 + tx];
    __syncthreads();
    float sc = scale[c0 + tx], sh = shift[c0 + tx];
    #pragma unroll
    for (int j = 0; j < 32; j += 8) {
        size_t idx = (size_t)(n * LL + l0 + ty + j) * CC + c0 + tx;
        out[idx] = fmaf(d[idx], sc, sh) + tile[tx][ty + j];
    }
}

// ---------------- host orchestration ----------------
#define MMA_SMEM (4 * 128 * LDA * 2)   // 139264 bytes

extern "C" void kernel_launch(void* const* d_in, const int* in_sizes, int n_in,
                              void* d_out, int out_size) {
    const float* x     = (const float*)d_in[0];
    const float* Wv    = (const float*)d_in[1];
    const float* bv    = (const float*)d_in[2];
    const float* Wom   = (const float*)d_in[3];
    const float* bom   = (const float*)d_in[4];
    const float* Wo    = (const float*)d_in[5];
    const float* gamma = (const float*)d_in[6];
    const float* beta  = (const float*)d_in[7];
    const float* Wc    = (const float*)d_in[8];
    float* out = (float*)d_out;

    float *tp, *vop, *sampp, *dp, *partp, *scalep, *shiftp, *bcatp;
    __nv_bfloat16 *wcat_h, *wcat_l, *wot_h, *wot_l, *wc_h, *wc_l;
    cudaGetSymbolAddress((void**)&tp,     g_t);
    cudaGetSymbolAddress((void**)&vop,    g_vo);
    cudaGetSymbolAddress((void**)&sampp,  g_samp);
    cudaGetSymbolAddress((void**)&dp,     g_d);
    cudaGetSymbolAddress((void**)&partp,  g_part);
    cudaGetSymbolAddress((void**)&scalep, g_scale);
    cudaGetSymbolAddress((void**)&shiftp, g_shift);
    cudaGetSymbolAddress((void**)&bcatp,  g_bcat);
    cudaGetSymbolAddress((void**)&wcat_h, g_WcatT_hi);
    cudaGetSymbolAddress((void**)&wcat_l, g_WcatT_lo);
    cudaGetSymbolAddress((void**)&wot_h,  g_WoT_hi);
    cudaGetSymbolAddress((void**)&wot_l,  g_WoT_lo);
    cudaGetSymbolAddress((void**)&wc_h,   g_Wc_hi);
    cudaGetSymbolAddress((void**)&wc_l,   g_Wc_lo);

    cudaFuncSetAttribute(mma_gemm_kernel, cudaFuncAttributeMaxDynamicSharedMemorySize, MMA_SMEM);

    dim3 tBlock(32, 8);
    dim3 tGrid(LL / 32, CC / 32, NB);
    dim3 gridVO(2, NL / 128);     // N=256
    dim3 grid128(1, NL / 128);    // N=128

    // layout prep
    t_c2l_kernel<<<tGrid, tBlock>>>(x, tp);
    pack_w_kernel<<<256, 128>>>(Wv, bv, Wom, bom, Wo, Wc, bcatp);

    // ---- DCN block 1 ----
    mma_gemm_kernel<<<gridVO, 256, MMA_SMEM>>>(tp, wcat_h, wcat_l, bcatp, vop, VOST, nullptr, nullptr);
    sample_kernel<<<NL / 8, 256>>>(vop, sampp);
    mma_gemm_kernel<<<grid128, 256, MMA_SMEM>>>(sampp, wot_h, wot_l, nullptr, dp, CC, nullptr, nullptr);
    bn_stats_kernel<<<64, 256>>>(dp, partp);
    bn_final_kernel<<<1, 128>>>(partp, gamma, beta, scalep, shiftp);

    // ---- DCN block 2 (BN+ReLU fused into A staging of VO GEMM) ----
    mma_gemm_kernel<<<gridVO, 256, MMA_SMEM>>>(dp, wcat_h, wcat_l, bcatp, vop, VOST, scalep, shiftp);
    sample_kernel<<<NL / 8, 256>>>(vop, sampp);
    mma_gemm_kernel<<<grid128, 256, MMA_SMEM>>>(sampp, wot_h, wot_l, nullptr, dp, CC, nullptr, nullptr);
    bn_stats_kernel<<<64, 256>>>(dp, partp);
    bn_final_kernel<<<1, 128>>>(partp, gamma, beta, scalep, shiftp);
    bn_resid_kernel<<<tGrid, tBlock>>>(dp, scalep, shiftp, x, tp);

    // ---- final channel mix + layout ----
    mma_gemm_kernel<<<grid128, 256, MMA_SMEM>>>(tp, wc_h, wc_l, nullptr, sampp, CC, nullptr, nullptr);
    t_l2c_kernel<<<tGrid, tBlock>>>(sampp, out);
}

// round 6
// speedup vs baseline: 2.1123x; 1.0733x over previous
#include <cuda_runtime.h>
#include <cuda_bf16.h>
#include <cstdint>

// Problem constants
#define NB   4
#define CC   128
#define HH   64
#define WW   64
#define LL   (HH*WW)          // 4096
#define NL   (NB*LL)          // 16384
#define GG   4
#define KK   9
#define CG   32               // CC/GG
#define OM   108              // G*3*K
#define VOST 256              // combined value+om row stride
#define EPSF 1e-5f
#define LDA  136              // padded bf16 row length (272B -> conflict-free ldmatrix)

__device__ __forceinline__ uint32_t smem_to_u32(const void* p) {
    uint32_t a;
    asm("{ .reg .u64 t; cvta.to.shared.u64 t, %1; cvt.u32.u64 %0, t; }" : "=r"(a) : "l"(p));
    return a;
}

__device__ __forceinline__ void ldm_x4(uint32_t addr, uint32_t& r0, uint32_t& r1,
                                       uint32_t& r2, uint32_t& r3) {
    asm volatile("ldmatrix.sync.aligned.m8n8.x4.shared.b16 {%0,%1,%2,%3}, [%4];"
                 : "=r"(r0), "=r"(r1), "=r"(r2), "=r"(r3) : "r"(addr));
}

__device__ __forceinline__ void mma16816(float* d, const uint32_t* a, const uint32_t* b) {
    asm volatile(
        "mma.sync.aligned.m16n8k16.row.col.f32.bf16.bf16.f32 "
        "{%0,%1,%2,%3}, {%4,%5,%6,%7}, {%8,%9}, {%0,%1,%2,%3};"
        : "+f"(d[0]), "+f"(d[1]), "+f"(d[2]), "+f"(d[3])
        : "r"(a[0]), "r"(a[1]), "r"(a[2]), "r"(a[3]), "r"(b[0]), "r"(b[1]));
}

// ---------------- scratch (device globals; no allocation allowed) ----------------
__device__ float g_t   [NL*CC];
__device__ float g_vo  [NL*VOST];
__device__ float g_samp[NL*CC];
__device__ float g_d   [NL*CC];
__device__ float g_part[2*128*CC];
__device__ float g_scale[CC];
__device__ float g_shift[CC];
__device__ float g_bcat[VOST];
__device__ __nv_bfloat16 g_WcatT_hi[VOST*CC];  // [n=256][k=128] = {Wv|Wom}^T
__device__ __nv_bfloat16 g_WcatT_lo[VOST*CC];
__device__ __nv_bfloat16 g_WoT_hi[CC*CC];      // [n][k] = Wo[k][n]
__device__ __nv_bfloat16 g_WoT_lo[CC*CC];
__device__ __nv_bfloat16 g_Wc_hi[CC*CC];       // [o][c] = Wc as-is
__device__ __nv_bfloat16 g_Wc_lo[CC*CC];

// ---------------- weight packing + bf16 split (once per launch) ----------------
__device__ __forceinline__ void split_store(float v, __nv_bfloat16* hi, __nv_bfloat16* lo, int idx) {
    __nv_bfloat16 h = __float2bfloat16_rn(v);
    hi[idx] = h;
    lo[idx] = __float2bfloat16_rn(v - __bfloat162float(h));
}

__global__ void pack_w_kernel(const float* __restrict__ Wv, const float* __restrict__ bv,
                              const float* __restrict__ Wom, const float* __restrict__ bom,
                              const float* __restrict__ Wo, const float* __restrict__ Wc,
                              float* __restrict__ bcat) {
    int n = blockIdx.x;    // 0..255
    int k = threadIdx.x;   // 0..127
    float v = 0.f;
    if (n < CC)           v = Wv[k * CC + n];
    else if (n < CC + OM) v = Wom[k * OM + (n - CC)];
    split_store(v, g_WcatT_hi, g_WcatT_lo, n * CC + k);
    if (n < CC) {
        split_store(Wo[k * CC + n], g_WoT_hi, g_WoT_lo, n * CC + k);
        split_store(Wc[n * CC + k], g_Wc_hi,  g_Wc_lo,  n * CC + k);
    }
    if (k == 0) {
        float b = 0.f;
        if (n < CC)           b = bv[n];
        else if (n < CC + OM) b = bom[n - CC];
        bcat[n] = b;
    }
}

// ---------------- transposes ----------------
__global__ void t_c2l_kernel(const float* __restrict__ in, float* __restrict__ out) {
    __shared__ float tile[32][33];
    int n = blockIdx.z, l0 = blockIdx.x * 32, c0 = blockIdx.y * 32;
    const float* ip = in  + (size_t)n * CC * LL;
    float*       op = out + (size_t)n * CC * LL;
    int tx = threadIdx.x, ty = threadIdx.y;
    #pragma unroll
    for (int j = 0; j < 32; j += 8)
        tile[ty + j][tx] = ip[(size_t)(c0 + ty + j) * LL + l0 + tx];
    __syncthreads();
    #pragma unroll
    for (int j = 0; j < 32; j += 8)
        op[(size_t)(l0 + ty + j) * CC + c0 + tx] = tile[tx][ty + j];
}

__global__ void t_l2c_kernel(const float* __restrict__ in, float* __restrict__ out) {
    __shared__ float tile[32][33];
    int n = blockIdx.z, l0 = blockIdx.x * 32, c0 = blockIdx.y * 32;
    const float* ip = in  + (size_t)n * CC * LL;
    float*       op = out + (size_t)n * CC * LL;
    int tx = threadIdx.x, ty = threadIdx.y;
    #pragma unroll
    for (int j = 0; j < 32; j += 8)
        tile[ty + j][tx] = ip[(size_t)(l0 + ty + j) * CC + c0 + tx];
    __syncthreads();
    #pragma unroll
    for (int j = 0; j < 32; j += 8)
        op[(size_t)(c0 + ty + j) * LL + l0 + tx] = tile[tx][ty + j];
}

// ---------------- HMMA GEMM: C[M,N] = A[M,128] @ B^T (+bias) ----------------
// bf16 split: D = Ahi*Bhi + Alo*Bhi + Ahi*Blo, fp32 accumulate.
// CTA = 128x128 tile, 256 threads (8 warps, 2M x 4N), warp = 64x32.
// Optional A transform relu(a*ascale[k]+ashift[k]); optional BN partial stats
// (part != null requires N==128, bn0==0).
__global__ __launch_bounds__(256, 1)
void mma_gemm_kernel(const float* __restrict__ A,
                     const __nv_bfloat16* __restrict__ Bhi,
                     const __nv_bfloat16* __restrict__ Blo,
                     const float* __restrict__ bias,
                     float* __restrict__ C, int ldc,
                     const float* __restrict__ ascale, const float* __restrict__ ashift,
                     float* __restrict__ part) {
    extern __shared__ __nv_bfloat16 sm[];
    __nv_bfloat16* sAh = sm;                 // [128][LDA]
    __nv_bfloat16* sAl = sAh + 128 * LDA;
    __nv_bfloat16* sBh = sAl + 128 * LDA;
    __nv_bfloat16* sBl = sBh + 128 * LDA;

    int tid = threadIdx.x;
    int bm0 = blockIdx.y * 128;
    int bn0 = blockIdx.x * 128;

    // ---- stage A: fp32 -> bf16 hi/lo (+ optional BN+ReLU) ----
    {
        int row = tid >> 1, kh = (tid & 1) * 64;
        const float* ar = A + (size_t)(bm0 + row) * 128 + kh;
        __nv_bfloat16* dh = sAh + row * LDA + kh;
        __nv_bfloat16* dl = sAl + row * LDA + kh;
        #pragma unroll
        for (int i = 0; i < 64; i += 8) {
            float v[8];
            *(float4*)&v[0] = *(const float4*)(ar + i);
            *(float4*)&v[4] = *(const float4*)(ar + i + 4);
            if (ascale) {
                #pragma unroll
                for (int j = 0; j < 8; j++)
                    v[j] = fmaxf(fmaf(v[j], ascale[kh + i + j], ashift[kh + i + j]), 0.f);
            }
            uint32_t h[4], l[4];
            #pragma unroll
            for (int p = 0; p < 4; p++) {
                __nv_bfloat16 h0 = __float2bfloat16_rn(v[2 * p]);
                __nv_bfloat16 h1 = __float2bfloat16_rn(v[2 * p + 1]);
                float l0 = v[2 * p] - __bfloat162float(h0);
                float l1 = v[2 * p + 1] - __bfloat162float(h1);
                __nv_bfloat162 hp; hp.x = h0; hp.y = h1;
                __nv_bfloat162 lp; lp.x = __float2bfloat16_rn(l0); lp.y = __float2bfloat16_rn(l1);
                h[p] = *reinterpret_cast<uint32_t*>(&hp);
                l[p] = *reinterpret_cast<uint32_t*>(&lp);
            }
            *(uint4*)(dh + i) = make_uint4(h[0], h[1], h[2], h[3]);
            *(uint4*)(dl + i) = make_uint4(l[0], l[1], l[2], l[3]);
        }
    }
    // ---- stage B: bf16 copy ----
    {
        int row = tid >> 1, kh = (tid & 1) * 64;
        const uint4* bh = (const uint4*)(Bhi + (size_t)(bn0 + row) * 128 + kh);
        const uint4* bl = (const uint4*)(Blo + (size_t)(bn0 + row) * 128 + kh);
        uint4* dh = (uint4*)(sBh + row * LDA + kh);
        uint4* dl = (uint4*)(sBl + row * LDA + kh);
        #pragma unroll
        for (int i = 0; i < 8; i++) { dh[i] = bh[i]; dl[i] = bl[i]; }
    }
    __syncthreads();

    int wid = tid >> 5, lane = tid & 31;
    int wm = (wid >> 2) * 64;      // warp M origin within tile
    int wn = (wid & 3) * 32;       // warp N origin within tile

    uint32_t baseA = smem_to_u32(sAh);
    uint32_t dAlo  = (uint32_t)(128 * LDA * 2);
    uint32_t baseB = smem_to_u32(sBh);
    uint32_t dBlo  = dAlo;

    int a_r = (lane & 7) + ((lane >> 3) & 1) * 8;
    int a_c = ((lane >> 4) & 1) * 8;
    int b_r = (lane & 7) + ((lane >> 4) & 1) * 8;
    int b_c = ((lane >> 3) & 1) * 8;

    float acc[4][4][4];
    #pragma unroll
    for (int i = 0; i < 4; i++)
        #pragma unroll
        for (int j = 0; j < 4; j++)
            #pragma unroll
            for (int q = 0; q < 4; q++) acc[i][j][q] = 0.f;

    #pragma unroll
    for (int k0 = 0; k0 < 128; k0 += 16) {
        uint32_t ah[4][4], al[4][4], bh[4][2], bl[4][2];
        #pragma unroll
        for (int mi = 0; mi < 4; mi++) {
            uint32_t off = (uint32_t)((wm + mi * 16 + a_r) * LDA + k0 + a_c) * 2;
            ldm_x4(baseA + off,        ah[mi][0], ah[mi][1], ah[mi][2], ah[mi][3]);
            ldm_x4(baseA + dAlo + off, al[mi][0], al[mi][1], al[mi][2], al[mi][3]);
        }
        #pragma unroll
        for (int p = 0; p < 2; p++) {
            uint32_t off = (uint32_t)((wn + p * 16 + b_r) * LDA + k0 + b_c) * 2;
            ldm_x4(baseB + off,        bh[2*p][0], bh[2*p][1], bh[2*p+1][0], bh[2*p+1][1]);
            ldm_x4(baseB + dBlo + off, bl[2*p][0], bl[2*p][1], bl[2*p+1][0], bl[2*p+1][1]);
        }
        #pragma unroll
        for (int mi = 0; mi < 4; mi++)
            #pragma unroll
            for (int nj = 0; nj < 4; nj++) {
                mma16816(acc[mi][nj], ah[mi], bh[nj]);
                mma16816(acc[mi][nj], al[mi], bh[nj]);
                mma16816(acc[mi][nj], ah[mi], bl[nj]);
            }
    }

    // ---- epilogue (+ optional BN partial sums) ----
    int q = lane >> 2, idx = lane & 3;
    float s[8] = {}, s2[8] = {};
    #pragma unroll
    for (int mi = 0; mi < 4; mi++) {
        int r0 = bm0 + wm + mi * 16 + q;
        #pragma unroll
        for (int nj = 0; nj < 4; nj++) {
            int c = bn0 + wn + nj * 8 + idx * 2;
            float2 v0 = make_float2(acc[mi][nj][0], acc[mi][nj][1]);
            float2 v1 = make_float2(acc[mi][nj][2], acc[mi][nj][3]);
            if (bias) {
                float2 b = *(const float2*)&bias[c];
                v0.x += b.x; v0.y += b.y; v1.x += b.x; v1.y += b.y;
            }
            if (part) {
                s[nj*2]    += v0.x + v1.x;
                s[nj*2+1]  += v0.y + v1.y;
                s2[nj*2]   = fmaf(v0.x, v0.x, fmaf(v1.x, v1.x, s2[nj*2]));
                s2[nj*2+1] = fmaf(v0.y, v0.y, fmaf(v1.y, v1.y, s2[nj*2+1]));
            }
            *(float2*)&C[(size_t)r0 * ldc + c]       = v0;
            *(float2*)&C[(size_t)(r0 + 8) * ldc + c] = v1;
        }
    }

    if (part) {
        __syncthreads();                       // all ldmatrix reads done
        float* red  = (float*)sm;              // [128 cols][16 contributors]
        float* red2 = red + 2048;
        int r = q + ((wid >> 2) << 3);         // 0..15
        #pragma unroll
        for (int nj = 0; nj < 4; nj++) {
            #pragma unroll
            for (int t = 0; t < 2; t++) {
                int c = wn + nj * 8 + idx * 2 + t;
                red [c * 16 + r] = s[nj*2+t];
                red2[c * 16 + r] = s2[nj*2+t];
            }
        }
        __syncthreads();
        if (tid < 128) {
            float a0 = 0.f, a1 = 0.f;
            #pragma unroll
            for (int t = 0; t < 16; t++) { a0 += red[tid * 16 + t]; a1 += red2[tid * 16 + t]; }
            part[blockIdx.y * CC + tid]            = a0;
            part[128 * CC + blockIdx.y * CC + tid] = a1;
        }
    }
}

// ---------------- deformable sampling: 2 positions/warp, batched loads ----------------
__global__ __launch_bounds__(256)
void sample_kernel(const float* __restrict__ vo, float* __restrict__ out) {
    __shared__ float s_om[16][OM];
    int wid  = threadIdx.x >> 5;
    int lane = threadIdx.x & 31;
    int pos0 = (blockIdx.x * 8 + wid) * 2;   // even; pair never straddles image
    int g = lane >> 3;

    const float* omp = vo + (size_t)pos0 * VOST + CC;
    #pragma unroll
    for (int i = lane; i < OM; i += 32) {
        s_om[2*wid][i]     = omp[i];
        s_om[2*wid + 1][i] = omp[VOST + i];
    }
    __syncwarp();

    int n  = pos0 >> 12;
    int l0 = pos0 & 4095;
    int h  = l0 >> 6;
    int w0 = l0 & 63;
    const float* vbase = vo + (size_t)n * (LL * VOST) + (lane << 2);
    const float* omg[2] = { &s_om[2*wid][g * 27], &s_om[2*wid + 1][g * 27] };

    float ax[2] = {}, ay[2] = {}, az[2] = {}, aw4[2] = {};

    #pragma unroll
    for (int k = 0; k < KK; k++) {
        int kdy = k / 3 - 1, kdx = k % 3 - 1;
        int   off[2][4];
        float cw[2][4];
        float mk[2];
        // phase 1: addresses + weights (ALU, branchy)
        #pragma unroll
        for (int p = 0; p < 2; p++) {
            float offx = omg[p][2 * k];
            float offy = omg[p][2 * k + 1];
            mk[p] = omg[p][18 + k];
            float ly = (float)(h + kdy) + offy;
            float lx = (float)(w0 + p + kdx) + offx;
            float y0f = floorf(ly), x0f = floorf(lx);
            float wy = ly - y0f, wx = lx - x0f;
            int y0 = (int)y0f, x0 = (int)x0f;
            if (y0 >= 0 && y0 < HH - 1 && x0 >= 0 && x0 < WW - 1) {
                int o = (y0 << 14) + (x0 << 8);
                off[p][0] = o;
                off[p][1] = o + VOST;
                off[p][2] = o + WW * VOST;
                off[p][3] = o + WW * VOST + VOST;
                cw[p][0] = (1.f - wy) * (1.f - wx);
                cw[p][1] = (1.f - wy) * wx;
                cw[p][2] = wy * (1.f - wx);
                cw[p][3] = wy * wx;
            } else {
                #pragma unroll
                for (int c = 0; c < 4; c++) {
                    int yi = y0 + (c >> 1), xi = x0 + (c & 1);
                    float wgt = ((c >> 1) ? wy : 1.f - wy) * ((c & 1) ? wx : 1.f - wx);
                    bool valid = (yi >= 0) && (yi < HH) && (xi >= 0) && (xi < WW);
                    int yc = min(max(yi, 0), HH - 1);
                    int xc = min(max(xi, 0), WW - 1);
                    off[p][c] = (yc << 14) + (xc << 8);
                    cw[p][c]  = valid ? wgt : 0.f;
                }
            }
        }
        // phase 2: issue all 8 loads
        float4 v[2][4];
        #pragma unroll
        for (int p = 0; p < 2; p++)
            #pragma unroll
            for (int c = 0; c < 4; c++)
                v[p][c] = *(const float4*)(vbase + off[p][c]);
        // phase 3: accumulate
        #pragma unroll
        for (int p = 0; p < 2; p++) {
            float sx = 0.f, sy = 0.f, sz = 0.f, sw = 0.f;
            #pragma unroll
            for (int c = 0; c < 4; c++) {
                sx = fmaf(v[p][c].x, cw[p][c], sx);
                sy = fmaf(v[p][c].y, cw[p][c], sy);
                sz = fmaf(v[p][c].z, cw[p][c], sz);
                sw = fmaf(v[p][c].w, cw[p][c], sw);
            }
            ax[p]  = fmaf(sx, mk[p], ax[p]);
            ay[p]  = fmaf(sy, mk[p], ay[p]);
            az[p]  = fmaf(sz, mk[p], az[p]);
            aw4[p] = fmaf(sw, mk[p], aw4[p]);
        }
    }
    *(float4*)&out[(size_t)pos0 * CC + (lane << 2)]       = make_float4(ax[0], ay[0], az[0], aw4[0]);
    *(float4*)&out[(size_t)(pos0 + 1) * CC + (lane << 2)] = make_float4(ax[1], ay[1], az[1], aw4[1]);
}

// ---------------- batchnorm finalize / apply ----------------
__global__ void bn_final_kernel(const float* __restrict__ part,
                                const float* __restrict__ gamma, const float* __restrict__ beta,
                                float* __restrict__ scale, float* __restrict__ shift) {
    int c = threadIdx.x;
    float s = 0.f, s2 = 0.f;
    #pragma unroll 8
    for (int b = 0; b < 128; b++) {
        s  += part[b * CC + c];
        s2 += part[128 * CC + b * CC + c];
    }
    float mean = s * (1.f / (float)NL);
    float var  = s2 * (1.f / (float)NL) - mean * mean;
    float sc   = gamma[c] * rsqrtf(var + EPSF);
    scale[c] = sc;
    shift[c] = beta[c] - mean * sc;
}

__global__ void bn_resid_kernel(const float* __restrict__ d,
                                const float* __restrict__ scale, const float* __restrict__ shift,
                                const float* __restrict__ x, float* __restrict__ out) {
    __shared__ float tile[32][33];
    int n = blockIdx.z, l0 = blockIdx.x * 32, c0 = blockIdx.y * 32;
    int tx = threadIdx.x, ty = threadIdx.y;
    const float* xp = x + (size_t)n * CC * LL;
    #pragma unroll
    for (int j = 0; j < 32; j += 8)
        tile[ty + j][tx] = xp[(size_t)(c0 + ty + j) * LL + l0 + tx];
    __syncthreads();
    float sc = scale[c0 + tx], sh = shift[c0 + tx];
    #pragma unroll
    for (int j = 0; j < 32; j += 8) {
        size_t idx = (size_t)(n * LL + l0 + ty + j) * CC + c0 + tx;
        out[idx] = fmaf(d[idx], sc, sh) + tile[tx][ty + j];
    }
}

// ---------------- host orchestration ----------------
#define MMA_SMEM (4 * 128 * LDA * 2)   // 139264 bytes

extern "C" void kernel_launch(void* const* d_in, const int* in_sizes, int n_in,
                              void* d_out, int out_size) {
    const float* x     = (const float*)d_in[0];
    const float* Wv    = (const float*)d_in[1];
    const float* bv    = (const float*)d_in[2];
    const float* Wom   = (const float*)d_in[3];
    const float* bom   = (const float*)d_in[4];
    const float* Wo    = (const float*)d_in[5];
    const float* gamma = (const float*)d_in[6];
    const float* beta  = (const float*)d_in[7];
    const float* Wc    = (const float*)d_in[8];
    float* out = (float*)d_out;

    float *tp, *vop, *sampp, *dp, *partp, *scalep, *shiftp, *bcatp;
    __nv_bfloat16 *wcat_h, *wcat_l, *wot_h, *wot_l, *wc_h, *wc_l;
    cudaGetSymbolAddress((void**)&tp,     g_t);
    cudaGetSymbolAddress((void**)&vop,    g_vo);
    cudaGetSymbolAddress((void**)&sampp,  g_samp);
    cudaGetSymbolAddress((void**)&dp,     g_d);
    cudaGetSymbolAddress((void**)&partp,  g_part);
    cudaGetSymbolAddress((void**)&scalep, g_scale);
    cudaGetSymbolAddress((void**)&shiftp, g_shift);
    cudaGetSymbolAddress((void**)&bcatp,  g_bcat);
    cudaGetSymbolAddress((void**)&wcat_h, g_WcatT_hi);
    cudaGetSymbolAddress((void**)&wcat_l, g_WcatT_lo);
    cudaGetSymbolAddress((void**)&wot_h,  g_WoT_hi);
    cudaGetSymbolAddress((void**)&wot_l,  g_WoT_lo);
    cudaGetSymbolAddress((void**)&wc_h,   g_Wc_hi);
    cudaGetSymbolAddress((void**)&wc_l,   g_Wc_lo);

    cudaFuncSetAttribute(mma_gemm_kernel, cudaFuncAttributeMaxDynamicSharedMemorySize, MMA_SMEM);

    dim3 tBlock(32, 8);
    dim3 tGrid(LL / 32, CC / 32, NB);
    dim3 gridVO(2, NL / 128);     // N=256
    dim3 grid128(1, NL / 128);    // N=128

    // layout prep
    t_c2l_kernel<<<tGrid, tBlock>>>(x, tp);
    pack_w_kernel<<<256, 128>>>(Wv, bv, Wom, bom, Wo, Wc, bcatp);

    // ---- DCN block 1 ----
    mma_gemm_kernel<<<gridVO, 256, MMA_SMEM>>>(tp, wcat_h, wcat_l, bcatp, vop, VOST, nullptr, nullptr, nullptr);
    sample_kernel<<<NL / 16, 256>>>(vop, sampp);
    mma_gemm_kernel<<<grid128, 256, MMA_SMEM>>>(sampp, wot_h, wot_l, nullptr, dp, CC, nullptr, nullptr, partp);
    bn_final_kernel<<<1, 128>>>(partp, gamma, beta, scalep, shiftp);

    // ---- DCN block 2 (BN+ReLU fused into A staging of VO GEMM) ----
    mma_gemm_kernel<<<gridVO, 256, MMA_SMEM>>>(dp, wcat_h, wcat_l, bcatp, vop, VOST, scalep, shiftp, nullptr);
    sample_kernel<<<NL / 16, 256>>>(vop, sampp);
    mma_gemm_kernel<<<grid128, 256, MMA_SMEM>>>(sampp, wot_h, wot_l, nullptr, dp, CC, nullptr, nullptr, partp);
    bn_final_kernel<<<1, 128>>>(partp, gamma, beta, scalep, shiftp);
    bn_resid_kernel<<<tGrid, tBlock>>>(dp, scalep, shiftp, x, tp);

    // ---- final channel mix + layout ----
    mma_gemm_kernel<<<grid128, 256, MMA_SMEM>>>(tp, wc_h, wc_l, nullptr, sampp, CC, nullptr, nullptr, nullptr);
    t_l2c_kernel<<<tGrid, tBlock>>>(sampp, out);
}